// round 15
// baseline (speedup 1.0000x reference)
#include <cuda_runtime.h>
#include <math_constants.h>

// Problem constants
#define BATCH  2
#define NQ     2048
#define NKEY   2048
#define DM     1024
#define DH     512      // gated half width (heads 0..7)
#define NHEAD8 8        // only heads 0..7 need attention

// ---------------------------------------------------------------------------
// Device scratch (no runtime allocation allowed)
// ---------------------------------------------------------------------------
__device__ float g_k [BATCH * NKEY * DH];   // gated key half   [B*Nk, 512]
__device__ float g_v [BATCH * NKEY * DH];   // gated value half [B*Nk, 512]
__device__ float g_ao[BATCH * NQ   * DH];   // attention output (heads 0..7) [B*Nq, 512]
__device__ float g_bo[DM];                  // effective output bias
__device__ int   g_mask_mode;               // 0 = uint8, 1 = int32, 2 = float32

// ---------------------------------------------------------------------------
// Kernel 0: detect mask storage dtype from word signatures.
//   int32 bool  -> every 32-bit word is 0 or 1
//   float32 bool-> every word is 0 or 0x3F800000
//   uint8 bool  -> words pack 4 random 0/1 bytes (neither signature)
// ---------------------------------------------------------------------------
__global__ void detect_mask_kernel(const unsigned int* __restrict__ AM)
{
    if (threadIdx.x == 0 && blockIdx.x == 0) {
        int c_i32 = 0, c_f32 = 0;
        #pragma unroll 4
        for (int i = 0; i < 256; i++) {
            unsigned int w = AM[i];
            if (w <= 1u) c_i32++;
            if (w == 0u || w == 0x3F800000u) c_f32++;
        }
        g_mask_mode = (c_i32 == 256) ? 1 : ((c_f32 == 256) ? 2 : 0);
    }
}

// ---------------------------------------------------------------------------
// Kernel 1: gating GEMM + sigmoid.
//   out[m, n] = sigmoid( X[m, :] . W[n, :] + b[n] + fb[n] ),  M=4096, N=512, K=1024
// ---------------------------------------------------------------------------
__global__ __launch_bounds__(256) void gate_kernel(
    const float* __restrict__ X, const float* __restrict__ W,
    const float* __restrict__ bias, const float* __restrict__ fb,
    int which)
{
    float* __restrict__ out = which ? g_v : g_k;

    const int t  = threadIdx.x;
    const int tx = t & 15, ty = t >> 4;
    const int n0 = blockIdx.x * 64;
    const int m0 = blockIdx.y * 64;

    __shared__ float As[16 * 68];       // transposed: As[k][m]
    __shared__ float Bs[16 * 68];       // transposed: Bs[k][n]

    float acc[4][4] = {};
    const int r  = t >> 2;              // 0..63
    const int kq = (t & 3) * 4;         // 0,4,8,12

    for (int kk = 0; kk < DM; kk += 16) {
        float4 av = *(const float4*)&X[(size_t)(m0 + r) * DM + kk + kq];
        float4 bv = *(const float4*)&W[(size_t)(n0 + r) * DM + kk + kq];
        __syncthreads();
        As[(kq + 0) * 68 + r] = av.x; As[(kq + 1) * 68 + r] = av.y;
        As[(kq + 2) * 68 + r] = av.z; As[(kq + 3) * 68 + r] = av.w;
        Bs[(kq + 0) * 68 + r] = bv.x; Bs[(kq + 1) * 68 + r] = bv.y;
        Bs[(kq + 2) * 68 + r] = bv.z; Bs[(kq + 3) * 68 + r] = bv.w;
        __syncthreads();
        #pragma unroll
        for (int k = 0; k < 16; k++) {
            float4 a4 = *(const float4*)&As[k * 68 + ty * 4];
            float4 b4 = *(const float4*)&Bs[k * 68 + tx * 4];
            float aa[4] = {a4.x, a4.y, a4.z, a4.w};
            float bb[4] = {b4.x, b4.y, b4.z, b4.w};
            #pragma unroll
            for (int i = 0; i < 4; i++)
                #pragma unroll
                for (int j = 0; j < 4; j++)
                    acc[i][j] = fmaf(aa[i], bb[j], acc[i][j]);
        }
    }

    #pragma unroll
    for (int i = 0; i < 4; i++) {
        float4 o4;
        float* oo = (float*)&o4;
        #pragma unroll
        for (int j = 0; j < 4; j++) {
            int n = n0 + tx * 4 + j;
            float v = acc[i][j] + bias[n] + fb[n];
            oo[j] = 1.0f / (1.0f + __expf(-v));
        }
        *(float4*)&out[(size_t)(m0 + ty * 4 + i) * DH + n0 + tx * 4] = o4;
    }
}

// ---------------------------------------------------------------------------
// Kernel 2: effective output bias folding in the constant summary heads:
//   g_bo[n] = bo[n] + sum_{c<512} v_sum[c] * Wo[n, 512 + c]
// ---------------------------------------------------------------------------
__global__ void biaseff_kernel(const float* __restrict__ Wo,
                               const float* __restrict__ bo,
                               const float* __restrict__ vsum)
{
    int n = blockIdx.x * 256 + threadIdx.x;   // 1024 total
    float s = bo[n];
    const float* wrow = Wo + (size_t)n * DM + DH;
    for (int c = 0; c < DH; c++) s = fmaf(vsum[c], wrow[c], s);
    g_bo[n] = s;
}

// ---------------------------------------------------------------------------
// Kernel 3: flash attention for heads 0..7.
//   grid (Nq/64, 8, B), 256 threads. 64x64 tiles, 4x4 micro-tiles.
//   Mask loaded per g_mask_mode (uint8 / int32 / float32 storage).
// ---------------------------------------------------------------------------
__global__ __launch_bounds__(256) void attn_kernel(
    const float* __restrict__ Q,
    const float* __restrict__ AW,
    const void*  __restrict__ AMv)
{
    __shared__ float Qs[64 * 64];   // Qs[d][r]
    __shared__ float Ks[64 * 64];   // Ks[d][c], reused as Ps[c][r]
    __shared__ float Vs[64 * 64];   // Vs[c][dv]

    const int t  = threadIdx.x;
    const int tx = t & 15, ty = t >> 4;
    const int q0 = blockIdx.x * 64;
    const int h  = blockIdx.y;
    const int b  = blockIdx.z;
    const int mmode = g_mask_mode;

    const unsigned char* AM8  = (const unsigned char*)AMv;
    const int*           AM32 = (const int*)AMv;
    const float*         AMf  = (const float*)AMv;

    // Load Q tile transposed: Qs[d][r]
    {
        const float* qg = Q + ((size_t)(b * NQ + q0)) * DM + h * 64;
        #pragma unroll
        for (int it = 0; it < 4; it++) {
            int lin = it * 256 + t;
            int r   = lin >> 4;
            int d4  = (lin & 15) * 4;
            float4 v = *(const float4*)&qg[(size_t)r * DM + d4];
            Qs[(d4 + 0) * 64 + r] = v.x;
            Qs[(d4 + 1) * 64 + r] = v.y;
            Qs[(d4 + 2) * 64 + r] = v.z;
            Qs[(d4 + 3) * 64 + r] = v.w;
        }
    }

    float o[4][4] = {};
    float mrow[4], lrow[4];
    #pragma unroll
    for (int i = 0; i < 4; i++) { mrow[i] = -CUDART_INF_F; lrow[i] = 0.0f; }

    const float* kg = g_k + ((size_t)(b * NKEY)) * DH + h * 64;
    const float* vg = g_v + ((size_t)(b * NKEY)) * DH + h * 64;
    const size_t wbase = (((size_t)(b * 16 + h)) * NQ + q0) * NKEY;

    for (int k0 = 0; k0 < NKEY; k0 += 64) {
        __syncthreads();   // prior-iteration Ps/Vs readers done (covers Qs on iter 0)

        // Load K tile transposed + V tile natural
        #pragma unroll
        for (int it = 0; it < 4; it++) {
            int lin = it * 256 + t;
            int c   = lin >> 4;
            int d4  = (lin & 15) * 4;
            float4 kv = *(const float4*)&kg[(size_t)(k0 + c) * DH + d4];
            Ks[(d4 + 0) * 64 + c] = kv.x;
            Ks[(d4 + 1) * 64 + c] = kv.y;
            Ks[(d4 + 2) * 64 + c] = kv.z;
            Ks[(d4 + 3) * 64 + c] = kv.w;
            float4 vv = *(const float4*)&vg[(size_t)(k0 + c) * DH + d4];
            *(float4*)&Vs[c * 64 + d4] = vv;
        }

        // Prefetch attention weights + mask (coalesced vector loads)
        float4 w4[4];
        unsigned char mb[4][4];
        #pragma unroll
        for (int i = 0; i < 4; i++) {
            size_t idx = wbase + (size_t)(ty * 4 + i) * NKEY + k0 + tx * 4;
            w4[i] = *(const float4*)&AW[idx];
            if (mmode == 1) {
                int4 m = *(const int4*)&AM32[idx];
                mb[i][0] = (unsigned char)(m.x != 0);
                mb[i][1] = (unsigned char)(m.y != 0);
                mb[i][2] = (unsigned char)(m.z != 0);
                mb[i][3] = (unsigned char)(m.w != 0);
            } else if (mmode == 0) {
                uchar4 m = *(const uchar4*)&AM8[idx];
                mb[i][0] = m.x; mb[i][1] = m.y; mb[i][2] = m.z; mb[i][3] = m.w;
            } else {
                float4 m = *(const float4*)&AMf[idx];
                mb[i][0] = (unsigned char)(m.x != 0.0f);
                mb[i][1] = (unsigned char)(m.y != 0.0f);
                mb[i][2] = (unsigned char)(m.z != 0.0f);
                mb[i][3] = (unsigned char)(m.w != 0.0f);
            }
        }
        __syncthreads();

        // S micro-GEMM: acc[i][j] = Q[r].K[c]
        float acc[4][4] = {};
        #pragma unroll
        for (int d = 0; d < 64; d++) {
            float4 a4 = *(const float4*)&Qs[d * 64 + ty * 4];
            float4 b4 = *(const float4*)&Ks[d * 64 + tx * 4];
            float aa[4] = {a4.x, a4.y, a4.z, a4.w};
            float bb[4] = {b4.x, b4.y, b4.z, b4.w};
            #pragma unroll
            for (int i = 0; i < 4; i++)
                #pragma unroll
                for (int j = 0; j < 4; j++)
                    acc[i][j] = fmaf(aa[i], bb[j], acc[i][j]);
        }

        // Scale, weight, mask, online softmax (row r = ty*4+i spans 16 tx lanes)
        #pragma unroll
        for (int i = 0; i < 4; i++) {
            const float* wf = (const float*)&w4[i];
            float s[4];
            float tmax = -CUDART_INF_F;
            #pragma unroll
            for (int j = 0; j < 4; j++) {
                s[j] = mb[i][j] ? -CUDART_INF_F : acc[i][j] * 0.125f * wf[j];
                tmax = fmaxf(tmax, s[j]);
            }
            #pragma unroll
            for (int off = 8; off >= 1; off >>= 1)
                tmax = fmaxf(tmax, __shfl_xor_sync(0xffffffffu, tmax, off, 16));
            float mnew  = fmaxf(mrow[i], tmax);
            float alpha = (mnew == -CUDART_INF_F) ? 1.0f : __expf(mrow[i] - mnew);
            float psum  = 0.0f;
            #pragma unroll
            for (int j = 0; j < 4; j++) {
                float p = (s[j] == -CUDART_INF_F) ? 0.0f : __expf(s[j] - mnew);
                acc[i][j] = p;
                psum += p;
            }
            #pragma unroll
            for (int off = 8; off >= 1; off >>= 1)
                psum += __shfl_xor_sync(0xffffffffu, psum, off, 16);
            lrow[i] = lrow[i] * alpha + psum;
            mrow[i] = mnew;
            #pragma unroll
            for (int j = 0; j < 4; j++) o[i][j] *= alpha;
        }

        __syncthreads();   // all Ks readers done -> safe to overwrite as Ps
        #pragma unroll
        for (int i = 0; i < 4; i++)
            #pragma unroll
            for (int j = 0; j < 4; j++)
                Ks[(tx * 4 + j) * 64 + ty * 4 + i] = acc[i][j];   // Ps[c][r]
        __syncthreads();

        // PV micro-GEMM: o[i][j] += P[r][c] * V[c][dv]
        #pragma unroll
        for (int c = 0; c < 64; c++) {
            float4 p4 = *(const float4*)&Ks[c * 64 + ty * 4];
            float4 v4 = *(const float4*)&Vs[c * 64 + tx * 4];
            float pp[4] = {p4.x, p4.y, p4.z, p4.w};
            float vv[4] = {v4.x, v4.y, v4.z, v4.w};
            #pragma unroll
            for (int i = 0; i < 4; i++)
                #pragma unroll
                for (int j = 0; j < 4; j++)
                    o[i][j] = fmaf(pp[i], vv[j], o[i][j]);
        }
    }

    // Normalize and store to g_ao [B*Nq, 512]
    #pragma unroll
    for (int i = 0; i < 4; i++) {
        float inv = 1.0f / lrow[i];
        float4 o4 = make_float4(o[i][0] * inv, o[i][1] * inv,
                                o[i][2] * inv, o[i][3] * inv);
        *(float4*)&g_ao[((size_t)(b * NQ + q0 + ty * 4 + i)) * DH + h * 64 + tx * 4] = o4;
    }
}

// ---------------------------------------------------------------------------
// Kernel 4: output projection.
//   out[m, n] = sum_{c<512} g_ao[m, c] * Wo[n, c] + g_bo[n]   M=4096, N=1024, K=512
// ---------------------------------------------------------------------------
__global__ __launch_bounds__(256) void proj_kernel(
    const float* __restrict__ Wo, float* __restrict__ out)
{
    const int t  = threadIdx.x;
    const int tx = t & 15, ty = t >> 4;
    const int n0 = blockIdx.x * 64;
    const int m0 = blockIdx.y * 64;

    __shared__ float As[16 * 68];
    __shared__ float Bs[16 * 68];

    float acc[4][4] = {};
    const int r  = t >> 2;
    const int kq = (t & 3) * 4;

    for (int kk = 0; kk < DH; kk += 16) {
        float4 av = *(const float4*)&g_ao[(size_t)(m0 + r) * DH + kk + kq];
        float4 bv = *(const float4*)&Wo[(size_t)(n0 + r) * DM + kk + kq];
        __syncthreads();
        As[(kq + 0) * 68 + r] = av.x; As[(kq + 1) * 68 + r] = av.y;
        As[(kq + 2) * 68 + r] = av.z; As[(kq + 3) * 68 + r] = av.w;
        Bs[(kq + 0) * 68 + r] = bv.x; Bs[(kq + 1) * 68 + r] = bv.y;
        Bs[(kq + 2) * 68 + r] = bv.z; Bs[(kq + 3) * 68 + r] = bv.w;
        __syncthreads();
        #pragma unroll
        for (int k = 0; k < 16; k++) {
            float4 a4 = *(const float4*)&As[k * 68 + ty * 4];
            float4 b4 = *(const float4*)&Bs[k * 68 + tx * 4];
            float aa[4] = {a4.x, a4.y, a4.z, a4.w};
            float bb[4] = {b4.x, b4.y, b4.z, b4.w};
            #pragma unroll
            for (int i = 0; i < 4; i++)
                #pragma unroll
                for (int j = 0; j < 4; j++)
                    acc[i][j] = fmaf(aa[i], bb[j], acc[i][j]);
        }
    }

    #pragma unroll
    for (int i = 0; i < 4; i++) {
        float4 o4;
        float* oo = (float*)&o4;
        #pragma unroll
        for (int j = 0; j < 4; j++)
            oo[j] = acc[i][j] + g_bo[n0 + tx * 4 + j];
        *(float4*)&out[(size_t)(m0 + ty * 4 + i) * DM + n0 + tx * 4] = o4;
    }
}

// ---------------------------------------------------------------------------
// Launch
// ---------------------------------------------------------------------------
extern "C" void kernel_launch(void* const* d_in, const int* in_sizes, int n_in,
                              void* d_out, int out_size)
{
    const float* queries = (const float*)d_in[0];
    const float* keys    = (const float*)d_in[1];
    const float* values  = (const float*)d_in[2];
    const void*  amask   = d_in[3];
    const float* aw      = (const float*)d_in[4];
    const float* Wk      = (const float*)d_in[5];
    const float* bk      = (const float*)d_in[6];
    const float* kfb     = (const float*)d_in[7];
    const float* Wv      = (const float*)d_in[8];
    const float* bv      = (const float*)d_in[9];
    const float* vfb     = (const float*)d_in[10];
    /* d_in[11] = k_sum: provably unused (summary-head outputs are
       independent of scores; softmax rows sum to 1) */
    const float* v_sum   = (const float*)d_in[12];
    const float* Wo      = (const float*)d_in[13];
    const float* bo      = (const float*)d_in[14];
    float*       out     = (float*)d_out;

    detect_mask_kernel<<<1, 32>>>((const unsigned int*)amask);
    gate_kernel<<<dim3(DH / 64, (BATCH * NKEY) / 64), 256>>>(keys,   Wk, bk, kfb, 0);
    gate_kernel<<<dim3(DH / 64, (BATCH * NKEY) / 64), 256>>>(values, Wv, bv, vfb, 1);
    biaseff_kernel<<<DM / 256, 256>>>(Wo, bo, v_sum);
    attn_kernel<<<dim3(NQ / 64, NHEAD8, BATCH), 256>>>(queries, aw, amask);
    proj_kernel<<<dim3(DM / 64, (BATCH * NQ) / 64), 256>>>(Wo, out);
}

// round 16
// speedup vs baseline: 1.0021x; 1.0021x over previous
#include <cuda_runtime.h>
#include <math_constants.h>

// Problem constants
#define BATCH  2
#define NQ     2048
#define NKEY   2048
#define DM     1024
#define DH     512      // gated half width (heads 0..7)
#define NHEAD8 8        // only heads 0..7 need attention

// ---------------------------------------------------------------------------
// Device scratch (no runtime allocation allowed)
// ---------------------------------------------------------------------------
__device__ float g_k [BATCH * NKEY * DH];   // gated key half   [B*Nk, 512]
__device__ float g_v [BATCH * NKEY * DH];   // gated value half [B*Nk, 512]
__device__ float g_ao[BATCH * NQ   * DH];   // attention output (heads 0..7) [B*Nq, 512]
__device__ float g_bo[DM];                  // effective output bias
__device__ int   g_mask_mode;               // 0 = uint8, 1 = int32, 2 = float32

// ---------------------------------------------------------------------------
// Kernel 0: detect mask storage dtype from word signatures.
//   int32 bool  -> every 32-bit word is 0 or 1
//   float32 bool-> every word is 0 or 0x3F800000
//   uint8 bool  -> words pack 4 random 0/1 bytes (neither signature)
// ---------------------------------------------------------------------------
__global__ void detect_mask_kernel(const unsigned int* __restrict__ AM)
{
    if (threadIdx.x == 0 && blockIdx.x == 0) {
        int c_i32 = 0, c_f32 = 0;
        #pragma unroll 4
        for (int i = 0; i < 256; i++) {
            unsigned int w = AM[i];
            if (w <= 1u) c_i32++;
            if (w == 0u || w == 0x3F800000u) c_f32++;
        }
        g_mask_mode = (c_i32 == 256) ? 1 : ((c_f32 == 256) ? 2 : 0);
    }
}

// ---------------------------------------------------------------------------
// Kernel 1: gating GEMM + sigmoid.
//   out[m, n] = sigmoid( X[m, :] . W[n, :] + b[n] + fb[n] ),  M=4096, N=512, K=1024
// ---------------------------------------------------------------------------
__global__ __launch_bounds__(256) void gate_kernel(
    const float* __restrict__ X, const float* __restrict__ W,
    const float* __restrict__ bias, const float* __restrict__ fb,
    int which)
{
    float* __restrict__ out = which ? g_v : g_k;

    const int t  = threadIdx.x;
    const int tx = t & 15, ty = t >> 4;
    const int n0 = blockIdx.x * 64;
    const int m0 = blockIdx.y * 64;

    __shared__ float As[16 * 68];       // transposed: As[k][m]
    __shared__ float Bs[16 * 68];       // transposed: Bs[k][n]

    float acc[4][4] = {};
    const int r  = t >> 2;              // 0..63
    const int kq = (t & 3) * 4;         // 0,4,8,12

    for (int kk = 0; kk < DM; kk += 16) {
        float4 av = *(const float4*)&X[(size_t)(m0 + r) * DM + kk + kq];
        float4 bv = *(const float4*)&W[(size_t)(n0 + r) * DM + kk + kq];
        __syncthreads();
        As[(kq + 0) * 68 + r] = av.x; As[(kq + 1) * 68 + r] = av.y;
        As[(kq + 2) * 68 + r] = av.z; As[(kq + 3) * 68 + r] = av.w;
        Bs[(kq + 0) * 68 + r] = bv.x; Bs[(kq + 1) * 68 + r] = bv.y;
        Bs[(kq + 2) * 68 + r] = bv.z; Bs[(kq + 3) * 68 + r] = bv.w;
        __syncthreads();
        #pragma unroll
        for (int k = 0; k < 16; k++) {
            float4 a4 = *(const float4*)&As[k * 68 + ty * 4];
            float4 b4 = *(const float4*)&Bs[k * 68 + tx * 4];
            float aa[4] = {a4.x, a4.y, a4.z, a4.w};
            float bb[4] = {b4.x, b4.y, b4.z, b4.w};
            #pragma unroll
            for (int i = 0; i < 4; i++)
                #pragma unroll
                for (int j = 0; j < 4; j++)
                    acc[i][j] = fmaf(aa[i], bb[j], acc[i][j]);
        }
    }

    #pragma unroll
    for (int i = 0; i < 4; i++) {
        float4 o4;
        float* oo = (float*)&o4;
        #pragma unroll
        for (int j = 0; j < 4; j++) {
            int n = n0 + tx * 4 + j;
            float v = acc[i][j] + bias[n] + fb[n];
            oo[j] = 1.0f / (1.0f + __expf(-v));
        }
        *(float4*)&out[(size_t)(m0 + ty * 4 + i) * DH + n0 + tx * 4] = o4;
    }
}

// ---------------------------------------------------------------------------
// Kernel 2: effective output bias folding in the constant summary heads:
//   g_bo[n] = bo[n] + sum_{c<512} v_sum[c] * Wo[n, 512 + c]
// ---------------------------------------------------------------------------
__global__ void biaseff_kernel(const float* __restrict__ Wo,
                               const float* __restrict__ bo,
                               const float* __restrict__ vsum)
{
    int n = blockIdx.x * 256 + threadIdx.x;   // 1024 total
    float s = bo[n];
    const float* wrow = Wo + (size_t)n * DM + DH;
    for (int c = 0; c < DH; c++) s = fmaf(vsum[c], wrow[c], s);
    g_bo[n] = s;
}

// ---------------------------------------------------------------------------
// Kernel 3: flash attention for heads 0..7.
//   grid (Nq/64, 8, B), 256 threads. 64x64 tiles, 4x4 micro-tiles.
//   Mask loaded per g_mask_mode (uint8 / int32 / float32 storage).
// ---------------------------------------------------------------------------
__global__ __launch_bounds__(256) void attn_kernel(
    const float* __restrict__ Q,
    const float* __restrict__ AW,
    const void*  __restrict__ AMv)
{
    __shared__ float Qs[64 * 64];   // Qs[d][r]
    __shared__ float Ks[64 * 64];   // Ks[d][c], reused as Ps[c][r]
    __shared__ float Vs[64 * 64];   // Vs[c][dv]

    const int t  = threadIdx.x;
    const int tx = t & 15, ty = t >> 4;
    const int q0 = blockIdx.x * 64;
    const int h  = blockIdx.y;
    const int b  = blockIdx.z;
    const int mmode = g_mask_mode;

    const unsigned char* AM8  = (const unsigned char*)AMv;
    const int*           AM32 = (const int*)AMv;
    const float*         AMf  = (const float*)AMv;

    // Load Q tile transposed: Qs[d][r]
    {
        const float* qg = Q + ((size_t)(b * NQ + q0)) * DM + h * 64;
        #pragma unroll
        for (int it = 0; it < 4; it++) {
            int lin = it * 256 + t;
            int r   = lin >> 4;
            int d4  = (lin & 15) * 4;
            float4 v = *(const float4*)&qg[(size_t)r * DM + d4];
            Qs[(d4 + 0) * 64 + r] = v.x;
            Qs[(d4 + 1) * 64 + r] = v.y;
            Qs[(d4 + 2) * 64 + r] = v.z;
            Qs[(d4 + 3) * 64 + r] = v.w;
        }
    }

    float o[4][4] = {};
    float mrow[4], lrow[4];
    #pragma unroll
    for (int i = 0; i < 4; i++) { mrow[i] = -CUDART_INF_F; lrow[i] = 0.0f; }

    const float* kg = g_k + ((size_t)(b * NKEY)) * DH + h * 64;
    const float* vg = g_v + ((size_t)(b * NKEY)) * DH + h * 64;
    const size_t wbase = (((size_t)(b * 16 + h)) * NQ + q0) * NKEY;

    for (int k0 = 0; k0 < NKEY; k0 += 64) {
        __syncthreads();   // prior-iteration Ps/Vs readers done (covers Qs on iter 0)

        // Load K tile transposed + V tile natural
        #pragma unroll
        for (int it = 0; it < 4; it++) {
            int lin = it * 256 + t;
            int c   = lin >> 4;
            int d4  = (lin & 15) * 4;
            float4 kv = *(const float4*)&kg[(size_t)(k0 + c) * DH + d4];
            Ks[(d4 + 0) * 64 + c] = kv.x;
            Ks[(d4 + 1) * 64 + c] = kv.y;
            Ks[(d4 + 2) * 64 + c] = kv.z;
            Ks[(d4 + 3) * 64 + c] = kv.w;
            float4 vv = *(const float4*)&vg[(size_t)(k0 + c) * DH + d4];
            *(float4*)&Vs[c * 64 + d4] = vv;
        }

        // Prefetch attention weights + mask (coalesced vector loads)
        float4 w4[4];
        unsigned char mb[4][4];
        #pragma unroll
        for (int i = 0; i < 4; i++) {
            size_t idx = wbase + (size_t)(ty * 4 + i) * NKEY + k0 + tx * 4;
            w4[i] = *(const float4*)&AW[idx];
            if (mmode == 1) {
                int4 m = *(const int4*)&AM32[idx];
                mb[i][0] = (unsigned char)(m.x != 0);
                mb[i][1] = (unsigned char)(m.y != 0);
                mb[i][2] = (unsigned char)(m.z != 0);
                mb[i][3] = (unsigned char)(m.w != 0);
            } else if (mmode == 0) {
                uchar4 m = *(const uchar4*)&AM8[idx];
                mb[i][0] = m.x; mb[i][1] = m.y; mb[i][2] = m.z; mb[i][3] = m.w;
            } else {
                float4 m = *(const float4*)&AMf[idx];
                mb[i][0] = (unsigned char)(m.x != 0.0f);
                mb[i][1] = (unsigned char)(m.y != 0.0f);
                mb[i][2] = (unsigned char)(m.z != 0.0f);
                mb[i][3] = (unsigned char)(m.w != 0.0f);
            }
        }
        __syncthreads();

        // S micro-GEMM: acc[i][j] = Q[r].K[c]
        float acc[4][4] = {};
        #pragma unroll
        for (int d = 0; d < 64; d++) {
            float4 a4 = *(const float4*)&Qs[d * 64 + ty * 4];
            float4 b4 = *(const float4*)&Ks[d * 64 + tx * 4];
            float aa[4] = {a4.x, a4.y, a4.z, a4.w};
            float bb[4] = {b4.x, b4.y, b4.z, b4.w};
            #pragma unroll
            for (int i = 0; i < 4; i++)
                #pragma unroll
                for (int j = 0; j < 4; j++)
                    acc[i][j] = fmaf(aa[i], bb[j], acc[i][j]);
        }

        // Scale, weight, mask, online softmax (row r = ty*4+i spans 16 tx lanes)
        #pragma unroll
        for (int i = 0; i < 4; i++) {
            const float* wf = (const float*)&w4[i];
            float s[4];
            float tmax = -CUDART_INF_F;
            #pragma unroll
            for (int j = 0; j < 4; j++) {
                s[j] = mb[i][j] ? -CUDART_INF_F : acc[i][j] * 0.125f * wf[j];
                tmax = fmaxf(tmax, s[j]);
            }
            #pragma unroll
            for (int off = 8; off >= 1; off >>= 1)
                tmax = fmaxf(tmax, __shfl_xor_sync(0xffffffffu, tmax, off, 16));
            float mnew  = fmaxf(mrow[i], tmax);
            float alpha = (mnew == -CUDART_INF_F) ? 1.0f : __expf(mrow[i] - mnew);
            float psum  = 0.0f;
            #pragma unroll
            for (int j = 0; j < 4; j++) {
                float p = (s[j] == -CUDART_INF_F) ? 0.0f : __expf(s[j] - mnew);
                acc[i][j] = p;
                psum += p;
            }
            #pragma unroll
            for (int off = 8; off >= 1; off >>= 1)
                psum += __shfl_xor_sync(0xffffffffu, psum, off, 16);
            lrow[i] = lrow[i] * alpha + psum;
            mrow[i] = mnew;
            #pragma unroll
            for (int j = 0; j < 4; j++) o[i][j] *= alpha;
        }

        __syncthreads();   // all Ks readers done -> safe to overwrite as Ps
        #pragma unroll
        for (int i = 0; i < 4; i++)
            #pragma unroll
            for (int j = 0; j < 4; j++)
                Ks[(tx * 4 + j) * 64 + ty * 4 + i] = acc[i][j];   // Ps[c][r]
        __syncthreads();

        // PV micro-GEMM: o[i][j] += P[r][c] * V[c][dv]
        #pragma unroll
        for (int c = 0; c < 64; c++) {
            float4 p4 = *(const float4*)&Ks[c * 64 + ty * 4];
            float4 v4 = *(const float4*)&Vs[c * 64 + tx * 4];
            float pp[4] = {p4.x, p4.y, p4.z, p4.w};
            float vv[4] = {v4.x, v4.y, v4.z, v4.w};
            #pragma unroll
            for (int i = 0; i < 4; i++)
                #pragma unroll
                for (int j = 0; j < 4; j++)
                    o[i][j] = fmaf(pp[i], vv[j], o[i][j]);
        }
    }

    // Normalize and store to g_ao [B*Nq, 512]
    #pragma unroll
    for (int i = 0; i < 4; i++) {
        float inv = 1.0f / lrow[i];
        float4 o4 = make_float4(o[i][0] * inv, o[i][1] * inv,
                                o[i][2] * inv, o[i][3] * inv);
        *(float4*)&g_ao[((size_t)(b * NQ + q0 + ty * 4 + i)) * DH + h * 64 + tx * 4] = o4;
    }
}

// ---------------------------------------------------------------------------
// Kernel 4: output projection.
//   out[m, n] = sum_{c<512} g_ao[m, c] * Wo[n, c] + g_bo[n]   M=4096, N=1024, K=512
// ---------------------------------------------------------------------------
__global__ __launch_bounds__(256) void proj_kernel(
    const float* __restrict__ Wo, float* __restrict__ out)
{
    const int t  = threadIdx.x;
    const int tx = t & 15, ty = t >> 4;
    const int n0 = blockIdx.x * 64;
    const int m0 = blockIdx.y * 64;

    __shared__ float As[16 * 68];
    __shared__ float Bs[16 * 68];

    float acc[4][4] = {};
    const int r  = t >> 2;
    const int kq = (t & 3) * 4;

    for (int kk = 0; kk < DH; kk += 16) {
        float4 av = *(const float4*)&g_ao[(size_t)(m0 + r) * DH + kk + kq];
        float4 bv = *(const float4*)&Wo[(size_t)(n0 + r) * DM + kk + kq];
        __syncthreads();
        As[(kq + 0) * 68 + r] = av.x; As[(kq + 1) * 68 + r] = av.y;
        As[(kq + 2) * 68 + r] = av.z; As[(kq + 3) * 68 + r] = av.w;
        Bs[(kq + 0) * 68 + r] = bv.x; Bs[(kq + 1) * 68 + r] = bv.y;
        Bs[(kq + 2) * 68 + r] = bv.z; Bs[(kq + 3) * 68 + r] = bv.w;
        __syncthreads();
        #pragma unroll
        for (int k = 0; k < 16; k++) {
            float4 a4 = *(const float4*)&As[k * 68 + ty * 4];
            float4 b4 = *(const float4*)&Bs[k * 68 + tx * 4];
            float aa[4] = {a4.x, a4.y, a4.z, a4.w};
            float bb[4] = {b4.x, b4.y, b4.z, b4.w};
            #pragma unroll
            for (int i = 0; i < 4; i++)
                #pragma unroll
                for (int j = 0; j < 4; j++)
                    acc[i][j] = fmaf(aa[i], bb[j], acc[i][j]);
        }
    }

    #pragma unroll
    for (int i = 0; i < 4; i++) {
        float4 o4;
        float* oo = (float*)&o4;
        #pragma unroll
        for (int j = 0; j < 4; j++)
            oo[j] = acc[i][j] + g_bo[n0 + tx * 4 + j];
        *(float4*)&out[(size_t)(m0 + ty * 4 + i) * DM + n0 + tx * 4] = o4;
    }
}

// ---------------------------------------------------------------------------
// Launch
// ---------------------------------------------------------------------------
extern "C" void kernel_launch(void* const* d_in, const int* in_sizes, int n_in,
                              void* d_out, int out_size)
{
    const float* queries = (const float*)d_in[0];
    const float* keys    = (const float*)d_in[1];
    const float* values  = (const float*)d_in[2];
    const void*  amask   = d_in[3];
    const float* aw      = (const float*)d_in[4];
    const float* Wk      = (const float*)d_in[5];
    const float* bk      = (const float*)d_in[6];
    const float* kfb     = (const float*)d_in[7];
    const float* Wv      = (const float*)d_in[8];
    const float* bv      = (const float*)d_in[9];
    const float* vfb     = (const float*)d_in[10];
    /* d_in[11] = k_sum: provably unused (summary-head outputs are
       independent of scores; softmax rows sum to 1) */
    const float* v_sum   = (const float*)d_in[12];
    const float* Wo      = (const float*)d_in[13];
    const float* bo      = (const float*)d_in[14];
    float*       out     = (float*)d_out;

    detect_mask_kernel<<<1, 32>>>((const unsigned int*)amask);
    gate_kernel<<<dim3(DH / 64, (BATCH * NKEY) / 64), 256>>>(keys,   Wk, bk, kfb, 0);
    gate_kernel<<<dim3(DH / 64, (BATCH * NKEY) / 64), 256>>>(values, Wv, bv, vfb, 1);
    biaseff_kernel<<<DM / 256, 256>>>(Wo, bo, v_sum);
    attn_kernel<<<dim3(NQ / 64, NHEAD8, BATCH), 256>>>(queries, aw, amask);
    proj_kernel<<<dim3(DM / 64, (BATCH * NQ) / 64), 256>>>(Wo, out);
}